// round 1
// baseline (speedup 1.0000x reference)
#include <cuda_runtime.h>
#include <cuda_bf16.h>

// Problem shape (fixed by the dataset)
#define N_NODES 50000
#define D_IN    128
#define D_OUT   64

// Scratch for h = x @ W  (device global: no allocation allowed in kernel_launch)
__device__ float g_h[N_NODES * D_OUT];

// ---------------------------------------------------------------------------
// Kernel 1: h = x @ W     x:[N,128] W:[128,64] -> h:[N,64]
// Block: 128 threads, 32 rows per block. W (32KB) + x tile (16.5KB) in smem.
// Thread (tx,ty): tx in [0,16) -> 4 consecutive cols, ty in [0,8) -> 4 rows.
// ---------------------------------------------------------------------------
__global__ __launch_bounds__(128) void gemm_kernel(
    const float* __restrict__ x,
    const float* __restrict__ w,
    float* __restrict__ h,
    int n_nodes)
{
    __shared__ float ws[D_IN][D_OUT];        // 128*64*4 = 32 KB
    __shared__ float xs[32][D_IN + 4];       // pad 4 floats: row stride 132*4=528B (16B aligned)

    const int tid = threadIdx.x;             // 0..127
    const int tx  = tid & 15;                // col group (4 cols)
    const int ty  = tid >> 4;                // row group (4 rows)
    const int row0 = blockIdx.x * 32;

    // Load full W into smem (2048 float4 / 128 threads = 16 each)
    {
        const float4* w4 = reinterpret_cast<const float4*>(w);
        float4* ws4 = reinterpret_cast<float4*>(&ws[0][0]);
        #pragma unroll
        for (int i = 0; i < 16; i++)
            ws4[tid + i * 128] = w4[tid + i * 128];
    }

    // Load 32-row x tile (32*32 float4 / 128 = 8 each), guarded for tail
    {
        const float4* x4 = reinterpret_cast<const float4*>(x);
        #pragma unroll
        for (int i = 0; i < 8; i++) {
            int idx = tid + i * 128;         // 0..1023
            int r = idx >> 5;                // row in tile
            int c4 = idx & 31;               // float4 col
            float4 v = make_float4(0.f, 0.f, 0.f, 0.f);
            if (row0 + r < n_nodes)
                v = x4[(size_t)(row0 + r) * (D_IN / 4) + c4];
            *reinterpret_cast<float4*>(&xs[r][c4 * 4]) = v;
        }
    }
    __syncthreads();

    float acc[4][4];
    #pragma unroll
    for (int r = 0; r < 4; r++)
        #pragma unroll
        for (int c = 0; c < 4; c++)
            acc[r][c] = 0.f;

    #pragma unroll 8
    for (int k = 0; k < D_IN; k++) {
        float4 wv = *reinterpret_cast<const float4*>(&ws[k][tx * 4]);
        #pragma unroll
        for (int r = 0; r < 4; r++) {
            float xv = xs[ty * 4 + r][k];
            acc[r][0] += xv * wv.x;
            acc[r][1] += xv * wv.y;
            acc[r][2] += xv * wv.z;
            acc[r][3] += xv * wv.w;
        }
    }

    #pragma unroll
    for (int r = 0; r < 4; r++) {
        int row = row0 + ty * 4 + r;
        if (row < n_nodes) {
            float4 v = make_float4(acc[r][0], acc[r][1], acc[r][2], acc[r][3]);
            *reinterpret_cast<float4*>(&h[(size_t)row * D_OUT + tx * 4]) = v;
        }
    }
}

// ---------------------------------------------------------------------------
// Kernel 2: out[i][f] = bias[f]   (d_out is poisoned; must init)
// ---------------------------------------------------------------------------
__global__ void init_kernel(float* __restrict__ out, const float* __restrict__ bias, int n_total)
{
    int i = blockIdx.x * blockDim.x + threadIdx.x;
    if (i < n_total) out[i] = bias[i & (D_OUT - 1)];
}

// ---------------------------------------------------------------------------
// Kernel 3: segmented-reduction scatter over sorted edge_dst.
// blockDim = (64, 4): x = feature lane, y = edge group. Each group owns
// EPG consecutive edges; accumulate in register while dst is constant,
// atomicAdd once per (segment boundary within group).
// ---------------------------------------------------------------------------
#define EPG 32

__global__ __launch_bounds__(256) void scatter_kernel(
    const float* __restrict__ h,
    const int*   __restrict__ src,
    const int*   __restrict__ dst,
    const float* __restrict__ val,
    float*       __restrict__ out,
    int n_edges)
{
    const int f  = threadIdx.x;                               // 0..63
    const int g  = blockIdx.x * blockDim.y + threadIdx.y;     // edge group id
    const int e0 = g * EPG;
    if (e0 >= n_edges) return;
    const int e1 = min(e0 + EPG, n_edges);

    float acc = 0.f;
    int cur = __ldg(&dst[e0]);

    for (int e = e0; e < e1; e++) {
        int d = __ldg(&dst[e]);
        if (d != cur) {
            atomicAdd(&out[(size_t)cur * D_OUT + f], acc);
            acc = 0.f;
            cur = d;
        }
        float v = __ldg(&val[e]);
        int   s = __ldg(&src[e]);
        acc += v * __ldg(&h[(size_t)s * D_OUT + f]);
    }
    atomicAdd(&out[(size_t)cur * D_OUT + f], acc);
}

// ---------------------------------------------------------------------------
extern "C" void kernel_launch(void* const* d_in, const int* in_sizes, int n_in,
                              void* d_out, int out_size)
{
    const float* x    = (const float*)d_in[0];   // [N, 128]
    const int*   esrc = (const int*)  d_in[1];   // [E]
    const int*   edst = (const int*)  d_in[2];   // [E]
    const float* eval = (const float*)d_in[3];   // [E]
    const float* w    = (const float*)d_in[4];   // [128, 64]
    const float* bias = (const float*)d_in[5];   // [64]
    float* out = (float*)d_out;                  // [N, 64]

    const int n_nodes = in_sizes[0] / D_IN;
    const int n_edges = in_sizes[1];

    float* h;
    cudaGetSymbolAddress((void**)&h, g_h);

    // 1) h = x @ W
    {
        int blocks = (n_nodes + 31) / 32;
        gemm_kernel<<<blocks, 128>>>(x, w, h, n_nodes);
    }
    // 2) out = bias
    {
        int total = n_nodes * D_OUT;
        init_kernel<<<(total + 255) / 256, 256>>>(out, bias, total);
    }
    // 3) segmented scatter-add
    {
        int groups = (n_edges + EPG - 1) / EPG;
        dim3 blk(64, 4);
        int blocks = (groups + 3) / 4;
        scatter_kernel<<<blocks, blk>>>(h, esrc, edst, eval, out, n_edges);
    }
}

// round 3
// speedup vs baseline: 1.4338x; 1.4338x over previous
#include <cuda_runtime.h>
#include <mma.h>
#include <cstdint>

using namespace nvcuda;

#define N_NODES 50000
#define D_IN    128
#define D_OUT   64

// h scratch: h[row][c] = g_h4[row*16 + c/4]
__device__ float4 g_h4[N_NODES * (D_OUT / 4)];

// ---------------------------------------------------------------------------
// Kernel 1: h = x @ W via tf32 mma.sync (wmma m16n16k8).
// Block: 256 threads = 8 warps, 128 rows/block. Warp w owns rows
// [row0+16w, row0+16w+16) x all 64 cols (4 accum fragments).
// W staged in smem (pre-rounded to tf32), A fragments loaded from gmem.
// 50000 % 16 == 0 -> warp tiles are all-or-nothing at the tail.
// ---------------------------------------------------------------------------
#define WLD 72   // padded smem leading dim for W

__global__ __launch_bounds__(256) void gemm_tc_kernel(
    const float* __restrict__ x,
    const float* __restrict__ w,
    float* __restrict__ h,
    int n_nodes)
{
    __shared__ float ws[D_IN][WLD];   // 128*72*4 = 36.9 KB

    const int tid = threadIdx.x;
    const int wid = tid >> 5;
    const int row0 = blockIdx.x * 128;

    // Stage W (8192 elems / 256 thr = 32 each), pre-rounded to tf32
    #pragma unroll
    for (int i = tid; i < D_IN * D_OUT; i += 256) {
        int k = i >> 6, n = i & 63;
        ws[k][n] = wmma::__float_to_tf32(w[i]);
    }
    __syncthreads();

    const int wrow = row0 + wid * 16;
    if (wrow >= n_nodes) return;   // clean 16-row granularity

    wmma::fragment<wmma::accumulator, 16, 16, 8, float> c[4];
    #pragma unroll
    for (int n = 0; n < 4; n++) wmma::fill_fragment(c[n], 0.0f);

    const float* a_base = x + (size_t)wrow * D_IN;

    #pragma unroll
    for (int k = 0; k < 16; k++) {
        wmma::fragment<wmma::matrix_a, 16, 16, 8, wmma::precision::tf32, wmma::row_major> a;
        wmma::load_matrix_sync(a, a_base + k * 8, D_IN);
        #pragma unroll
        for (int t = 0; t < a.num_elements; t++)
            a.x[t] = wmma::__float_to_tf32(a.x[t]);

        #pragma unroll
        for (int n = 0; n < 4; n++) {
            wmma::fragment<wmma::matrix_b, 16, 16, 8, wmma::precision::tf32, wmma::row_major> b;
            wmma::load_matrix_sync(b, &ws[k * 8][n * 16], WLD);
            wmma::mma_sync(c[n], a, b, c[n]);
        }
    }

    float* hp = h + (size_t)wrow * D_OUT;
    #pragma unroll
    for (int n = 0; n < 4; n++)
        wmma::store_matrix_sync(hp + n * 16, c[n], D_OUT, wmma::mem_row_major);
}

// ---------------------------------------------------------------------------
// Kernel 2: out[i][f] = bias[f]
// ---------------------------------------------------------------------------
__global__ void init_kernel(float* __restrict__ out, const float* __restrict__ bias, int n_total)
{
    int i = blockIdx.x * blockDim.x + threadIdx.x;
    if (i < n_total) out[i] = bias[i & (D_OUT - 1)];
}

// ---------------------------------------------------------------------------
// Kernel 3: segmented scatter-add over sorted edge_dst, float4 feature lanes.
// 16 threads per edge group of EPG edges; register accumulate while dst
// constant, atomicAdd at segment boundaries.
// ---------------------------------------------------------------------------
#define EPG 32

__global__ __launch_bounds__(256) void scatter_kernel(
    const float4* __restrict__ h4,
    const int*    __restrict__ src,
    const int*    __restrict__ dst,
    const float*  __restrict__ val,
    float*        __restrict__ out,
    int n_edges)
{
    const int f4 = threadIdx.x & 15;                               // feature quad
    const int g  = (blockIdx.x * blockDim.x + threadIdx.x) >> 4;   // edge group
    const int e0 = g * EPG;
    if (e0 >= n_edges) return;
    const int e1 = min(e0 + EPG, n_edges);

    float4 acc = make_float4(0.f, 0.f, 0.f, 0.f);
    int cur = __ldg(&dst[e0]);

    #pragma unroll 4
    for (int e = e0; e < e1; e++) {
        int d = __ldg(&dst[e]);
        if (d != cur) {
            float* p = out + (size_t)cur * D_OUT + f4 * 4;
            atomicAdd(p + 0, acc.x); atomicAdd(p + 1, acc.y);
            atomicAdd(p + 2, acc.z); atomicAdd(p + 3, acc.w);
            acc = make_float4(0.f, 0.f, 0.f, 0.f);
            cur = d;
        }
        float  v  = __ldg(&val[e]);
        int    s  = __ldg(&src[e]);
        float4 hv = __ldg(&h4[(size_t)s * 16 + f4]);
        acc.x += v * hv.x; acc.y += v * hv.y;
        acc.z += v * hv.z; acc.w += v * hv.w;
    }
    {
        float* p = out + (size_t)cur * D_OUT + f4 * 4;
        atomicAdd(p + 0, acc.x); atomicAdd(p + 1, acc.y);
        atomicAdd(p + 2, acc.z); atomicAdd(p + 3, acc.w);
    }
}

// ---------------------------------------------------------------------------
extern "C" void kernel_launch(void* const* d_in, const int* in_sizes, int n_in,
                              void* d_out, int out_size)
{
    const float* x    = (const float*)d_in[0];   // [N, 128]
    const int*   esrc = (const int*)  d_in[1];   // [E]
    const int*   edst = (const int*)  d_in[2];   // [E]
    const float* eval = (const float*)d_in[3];   // [E]
    const float* w    = (const float*)d_in[4];   // [128, 64]
    const float* bias = (const float*)d_in[5];   // [64]
    float* out = (float*)d_out;                  // [N, 64]

    const int n_nodes = in_sizes[0] / D_IN;
    const int n_edges = in_sizes[1];

    float4* h4;
    cudaGetSymbolAddress((void**)&h4, g_h4);
    float* h = (float*)h4;

    // 1) h = x @ W  (tf32 mma.sync)
    {
        int blocks = (n_nodes + 127) / 128;
        gemm_tc_kernel<<<blocks, 256>>>(x, w, h, n_nodes);
    }
    // 2) out = bias
    {
        int total = n_nodes * D_OUT;
        init_kernel<<<(total + 255) / 256, 256>>>(out, bias, total);
    }
    // 3) segmented scatter-add
    {
        int groups = (n_edges + EPG - 1) / EPG;
        int threads = groups * 16;
        scatter_kernel<<<(threads + 255) / 256, 256>>>(h4, esrc, edst, eval, out, n_edges);
    }
}

// round 6
// speedup vs baseline: 1.5613x; 1.0889x over previous
#include <cuda_runtime.h>
#include <mma.h>
#include <cstdint>

using namespace nvcuda;

#define N_NODES 50000
#define D_IN    128
#define D_OUT   64

// h scratch: h[row][c] = g_h4[row*16 + c/4]
__device__ float4 g_h4[N_NODES * (D_OUT / 4)];
// CSR row starts built from sorted edge_dst
__device__ int g_row_start[N_NODES + 1];

// ---------------------------------------------------------------------------
// Kernel 1: h = x @ W via tf32 mma.sync, both operands staged in smem.
//   xs: [128][132] tf32 (A, row-major, ld=132 -> lane t hits bank t)
//   wt: [64][132]  tf32 (B=W^T, col-major frag ld=132 -> lane t hits bank t)
// Block: 256 thr / 8 warps, 128 rows; warp w owns rows [16w,16w+16) x 64 cols.
// ---------------------------------------------------------------------------
#define XS_LD 132
#define WT_LD 132
#define SMEM_WT_OFF (128 * XS_LD)                       // floats
#define GEMM_SMEM   ((128 * XS_LD + 64 * WT_LD) * 4)    // 101376 B

__global__ __launch_bounds__(256) void gemm_tc_kernel(
    const float* __restrict__ x,
    const float* __restrict__ w,
    float* __restrict__ h,
    int n_nodes)
{
    extern __shared__ float sm[];
    float* xs = sm;                  // [128][XS_LD]
    float* wt = sm + SMEM_WT_OFF;    // [64][WT_LD], wt[n][k]

    const int tid = threadIdx.x;
    const int wid = tid >> 5;
    const int row0 = blockIdx.x * 128;

    // Stage W^T (8192 elems): coalesced gmem read, conflict-free smem scatter
    #pragma unroll
    for (int i = tid; i < D_IN * D_OUT; i += 256) {
        int k = i >> 6, n = i & 63;
        wt[n * WT_LD + k] = wmma::__float_to_tf32(w[i]);
    }
    // Stage x tile: 128 rows x 32 float4, coalesced
    {
        const float4* x4 = (const float4*)x;
        #pragma unroll
        for (int i = tid; i < 128 * 32; i += 256) {
            int r = i >> 5, c4 = i & 31;
            if (row0 + r < n_nodes) {
                float4 v = x4[(size_t)(row0 + r) * 32 + c4];
                float* p = xs + r * XS_LD + c4 * 4;
                p[0] = wmma::__float_to_tf32(v.x);
                p[1] = wmma::__float_to_tf32(v.y);
                p[2] = wmma::__float_to_tf32(v.z);
                p[3] = wmma::__float_to_tf32(v.w);
            }
        }
    }
    __syncthreads();

    const int wrow = row0 + wid * 16;
    if (wrow >= n_nodes) return;    // 50000 % 16 == 0: tiles all-or-nothing

    wmma::fragment<wmma::accumulator, 16, 16, 8, float> c[4];
    #pragma unroll
    for (int n = 0; n < 4; n++) wmma::fill_fragment(c[n], 0.0f);

    const float* a_base = xs + wid * 16 * XS_LD;

    #pragma unroll
    for (int k = 0; k < 16; k++) {
        wmma::fragment<wmma::matrix_a, 16, 16, 8, wmma::precision::tf32, wmma::row_major> a;
        wmma::load_matrix_sync(a, a_base + k * 8, XS_LD);
        #pragma unroll
        for (int n = 0; n < 4; n++) {
            wmma::fragment<wmma::matrix_b, 16, 16, 8, wmma::precision::tf32, wmma::col_major> b;
            wmma::load_matrix_sync(b, wt + (n * 16) * WT_LD + k * 8, WT_LD);
            wmma::mma_sync(c[n], a, b, c[n]);
        }
    }

    float* hp = h + (size_t)wrow * D_OUT;
    #pragma unroll
    for (int n = 0; n < 4; n++)
        wmma::store_matrix_sync(hp + n * 16, c[n], D_OUT, wmma::mem_row_major);
}

// ---------------------------------------------------------------------------
// Kernel 2: build row_start from sorted dst.
// row_start[i] = first edge e with dst[e] >= i; row_start[n] = E.
// ---------------------------------------------------------------------------
__global__ void fill_rowstart_kernel(const int* __restrict__ dst,
                                     int* __restrict__ row_start,
                                     int n_edges, int n_nodes)
{
    int e = blockIdx.x * blockDim.x + threadIdx.x;
    if (e >= n_edges) return;
    int d = __ldg(&dst[e]);
    int prev = (e == 0) ? -1 : __ldg(&dst[e - 1]);
    for (int i = prev + 1; i <= d; i++) row_start[i] = e;
    if (e == n_edges - 1)
        for (int i = d + 1; i <= n_nodes; i++) row_start[i] = n_edges;
}

// ---------------------------------------------------------------------------
// Kernel 3: per-node CSR aggregation. 16 lanes per node (float4 feature lanes).
// out[i] = bias + sum_{e in [s,t)} val[e] * h[src[e]].  No atomics, no init.
// ---------------------------------------------------------------------------
__global__ __launch_bounds__(256) void agg_kernel(
    const float4* __restrict__ h4,
    const int*    __restrict__ src,
    const float*  __restrict__ val,
    const int*    __restrict__ row_start,
    const float4* __restrict__ bias4,
    float4*       __restrict__ out4,
    int n_nodes)
{
    const int f4   = threadIdx.x & 15;
    const int node = (blockIdx.x * blockDim.x + threadIdx.x) >> 4;
    if (node >= n_nodes) return;

    const int s = __ldg(&row_start[node]);
    const int t = __ldg(&row_start[node + 1]);

    float4 acc = __ldg(&bias4[f4]);

    #pragma unroll 4
    for (int e = s; e < t; e++) {
        float  v  = __ldg(&val[e]);
        int    sc = __ldg(&src[e]);
        float4 hv = __ldg(&h4[(size_t)sc * 16 + f4]);
        acc.x += v * hv.x; acc.y += v * hv.y;
        acc.z += v * hv.z; acc.w += v * hv.w;
    }
    out4[(size_t)node * 16 + f4] = acc;
}

// ---------------------------------------------------------------------------
extern "C" void kernel_launch(void* const* d_in, const int* in_sizes, int n_in,
                              void* d_out, int out_size)
{
    const float* x    = (const float*)d_in[0];   // [N, 128]
    const int*   esrc = (const int*)  d_in[1];   // [E]
    const int*   edst = (const int*)  d_in[2];   // [E]
    const float* eval = (const float*)d_in[3];   // [E]
    const float* w    = (const float*)d_in[4];   // [128, 64]
    const float* bias = (const float*)d_in[5];   // [64]
    float* out = (float*)d_out;                  // [N, 64]

    const int n_nodes = in_sizes[0] / D_IN;
    const int n_edges = in_sizes[1];

    float4* h4;
    cudaGetSymbolAddress((void**)&h4, g_h4);
    int* row_start;
    cudaGetSymbolAddress((void**)&row_start, g_row_start);

    // 1) CSR row starts (independent of gemm; cheap)
    fill_rowstart_kernel<<<(n_edges + 255) / 256, 256>>>(edst, row_start, n_edges, n_nodes);

    // 2) h = x @ W (tf32 mma.sync, smem-staged operands)
    {
        cudaFuncSetAttribute(gemm_tc_kernel,
                             cudaFuncAttributeMaxDynamicSharedMemorySize, GEMM_SMEM);
        int blocks = (n_nodes + 127) / 128;
        gemm_tc_kernel<<<blocks, 256, GEMM_SMEM>>>(x, w, (float*)h4, n_nodes);
    }

    // 3) out = bias + A @ h (per-node gather, no atomics)
    {
        int threads = n_nodes * 16;
        agg_kernel<<<(threads + 255) / 256, 256>>>(h4, esrc, eval, row_start,
                                                   (const float4*)bias, (float4*)out, n_nodes);
    }
}